// round 1
// baseline (speedup 1.0000x reference)
#include <cuda_runtime.h>
#include <cuda_bf16.h>
#include <cstdint>

#define SDIM 256
#define EDIM 32
#define VDIM 64
#define NMOL 64
#define NAF  16
#define NBT  5
#define MAXN 2048

// ---------------- device scratch (no allocs allowed) ----------------
__device__ float g_sh[MAXN * SDIM];        // s_h = silu(s@Ws+bs)
__device__ float g_raw[MAXN * 3];          // p + coords (pre-centering)
__device__ float g_cp[MAXN * 3];           // centered coords_pred
__device__ float g_sums[NMOL * 3];
__device__ float g_cnt[NMOL];
__device__ int   g_map[MAXN * MAXN];       // last-writer edge index per (j,i)

__device__ __forceinline__ float silu_f(float x) {
    // x * sigmoid(x), MUFU-based, ~1e-6 rel error
    return __fdividef(x, 1.0f + __expf(-x));
}

// ---------------- init: map=-1, sums/cnt=0 ----------------
__global__ void init_kernel(int N) {
    int idx = blockIdx.x * blockDim.x + threadIdx.x;
    int total = N * N;
    for (int i = idx; i < total; i += gridDim.x * blockDim.x) g_map[i] = -1;
    if (idx < NMOL * 3) g_sums[idx] = 0.0f;
    if (idx < NMOL)     g_cnt[idx]  = 0.0f;
}

// ---------------- s_h = silu(s @ Ws + bs), 16 rows/block ----------------
__global__ __launch_bounds__(256) void sh_kernel(
    const float* __restrict__ s, const float* __restrict__ Ws,
    const float* __restrict__ bs, int N)
{
    __shared__ float sX[16 * 256];
    __shared__ float sW[32 * 256];
    int tid = threadIdx.x, lane = tid & 31, wp = tid >> 5;
    int row0 = blockIdx.x * 16;

    for (int idx = tid; idx < 16 * 256; idx += 256) {
        int g = row0 * 256 + idx;
        sX[idx] = (g < N * 256) ? s[g] : 0.0f;
    }

    float acc[8][2];
#pragma unroll
    for (int u = 0; u < 8; u++) {
        float b = bs[lane + 32 * u];
        acc[u][0] = b; acc[u][1] = b;
    }

    for (int kc = 0; kc < 8; kc++) {
        __syncthreads();
        for (int idx = tid; idx < 8192; idx += 256)
            sW[idx] = Ws[kc * 32 * 256 + idx];
        __syncthreads();
#pragma unroll
        for (int kk = 0; kk < 32; kk++) {
            float w[8];
#pragma unroll
            for (int u = 0; u < 8; u++) w[u] = sW[kk * 256 + lane + 32 * u];
            float x0 = sX[(wp * 2 + 0) * 256 + kc * 32 + kk];
            float x1 = sX[(wp * 2 + 1) * 256 + kc * 32 + kk];
#pragma unroll
            for (int u = 0; u < 8; u++) {
                acc[u][0] += w[u] * x0;
                acc[u][1] += w[u] * x1;
            }
        }
    }
#pragma unroll
    for (int v = 0; v < 2; v++) {
        int r = row0 + wp * 2 + v;
        if (r < N) {
#pragma unroll
            for (int u = 0; u < 8; u++)
                g_sh[r * 256 + lane + 32 * u] = silu_f(acc[u][v]);
        }
    }
}

// ---------------- atoms_pred = s_h @ Wa + ba (one warp per node) ----------------
__global__ void atoms_kernel(const float* __restrict__ Wa, const float* __restrict__ ba,
                             float* __restrict__ out_atoms, int N)
{
    int wg = (blockIdx.x * blockDim.x + threadIdx.x) >> 5;
    int lane = threadIdx.x & 31;
    if (wg >= N) return;
    const float* row = g_sh + (size_t)wg * 256;
    float acc[NAF];
#pragma unroll
    for (int a = 0; a < NAF; a++) acc[a] = 0.0f;
#pragma unroll
    for (int m = 0; m < 8; m++) {
        int c = lane + 32 * m;
        float x = row[c];
#pragma unroll
        for (int a = 0; a < NAF; a++) acc[a] += x * Wa[c * NAF + a];
    }
#pragma unroll
    for (int a = 0; a < NAF; a++) {
#pragma unroll
        for (int off = 16; off; off >>= 1)
            acc[a] += __shfl_xor_sync(0xffffffffu, acc[a], off);
    }
#pragma unroll
    for (int a = 0; a < NAF; a++)
        if (lane == a) out_atoms[(size_t)wg * NAF + a] = acc[a] + ba[a];
}

// ---------------- coords = v@Wc; raw = p+coords; per-mol sums (one warp per node) ----------------
__global__ void coords_kernel(const float* __restrict__ v, const float* __restrict__ p,
                              const float* __restrict__ Wc, const int* __restrict__ batch, int N)
{
    int n = (blockIdx.x * blockDim.x + threadIdx.x) >> 5;
    int lane = threadIdx.x & 31;
    if (n >= N) return;
    const float* vb = v + (size_t)n * 3 * VDIM;
    float w0 = Wc[lane], w1 = Wc[32 + lane];
    float a0 = vb[lane] * w0 + vb[32 + lane] * w1;
    float a1 = vb[64 + lane] * w0 + vb[96 + lane] * w1;
    float a2 = vb[128 + lane] * w0 + vb[160 + lane] * w1;
#pragma unroll
    for (int off = 16; off; off >>= 1) {
        a0 += __shfl_xor_sync(0xffffffffu, a0, off);
        a1 += __shfl_xor_sync(0xffffffffu, a1, off);
        a2 += __shfl_xor_sync(0xffffffffu, a2, off);
    }
    if (lane == 0) {
        int b = batch[n];
        float r0 = p[n * 3 + 0] + a0;
        float r1 = p[n * 3 + 1] + a1;
        float r2 = p[n * 3 + 2] + a2;
        g_raw[n * 3 + 0] = r0; g_raw[n * 3 + 1] = r1; g_raw[n * 3 + 2] = r2;
        atomicAdd(&g_sums[b * 3 + 0], r0);
        atomicAdd(&g_sums[b * 3 + 1], r1);
        atomicAdd(&g_sums[b * 3 + 2], r2);
        atomicAdd(&g_cnt[b], 1.0f);
    }
}

// ---------------- subtract per-mol mean, write coords_pred ----------------
__global__ void finalize_coords_kernel(const int* __restrict__ batch,
                                       float* __restrict__ out_coords, int N)
{
    int idx = blockIdx.x * blockDim.x + threadIdx.x;
    if (idx >= N * 3) return;
    int n = idx / 3, d = idx % 3;
    int b = batch[n];
    float m = g_sums[b * 3 + d] / fmaxf(g_cnt[b], 1.0f);
    float cp = g_raw[idx] - m;
    g_cp[idx] = cp;
    out_coords[idx] = cp;
}

// ---------------- last-writer scatter for e_dense emulation ----------------
__global__ void scatter_kernel(const int* __restrict__ eidx, int N, int E)
{
    int k = blockIdx.x * blockDim.x + threadIdx.x;
    if (k >= E) return;
    int j = eidx[k];
    int i = eidx[E + k];
    atomicMax(&g_map[j * N + i], k);
}

// ---------------- fused per-edge network: 64 edges/block ----------------
// f = s_h[i]+s_h[j]+Esym@Wb+bb ; edge=[f,d] ; z=silu(edge@W0+b0) ; bonds=z@W1+b1
#define EDGE_PITCH 260
#define EDGE_SMEM_FLOATS (64 * EDGE_PITCH + 32 * 256 + 256 + 256)

__global__ __launch_bounds__(256, 2) void edge_kernel(
    const float* __restrict__ e, const int* __restrict__ eidx,
    const float* __restrict__ Wb, const float* __restrict__ bb,
    const float* __restrict__ W0, const float* __restrict__ b0,
    const float* __restrict__ W1, const float* __restrict__ b1,
    float* __restrict__ out_bonds, int N, int E)
{
    extern __shared__ float sm[];
    float* sEdge = sm;                       // [64][EDGE_PITCH], f + d at col 256
    float* sW    = sm + 64 * EDGE_PITCH;     // [32][256] : Wb, then W0 chunks
    float* sW0d  = sW + 32 * 256;            // W0 row 256 (d weights)
    float* sBB   = sW0d + 256;               // bb

    int tid = threadIdx.x, lane = tid & 31, wp = tid >> 5;
    int e0 = blockIdx.x * 64;

    for (int idx = tid; idx < 8192; idx += 256) sW[idx] = Wb[idx];
    if (tid < 256) { sBB[tid] = bb[tid]; sW0d[tid] = W0[256 * 256 + tid]; }
    __syncthreads();

    // ---- phase 1: build f rows (warp wp handles 8 edges) ----
    for (int v = 0; v < 8; v++) {
        int el = wp * 8 + v;
        int eg = e0 + el;
        float a[8];
        float dval = 0.0f;
        if (eg < E) {
            int j = eidx[eg];
            int i = eidx[E + eg];
            int k1 = g_map[j * N + i];
            int k2 = g_map[i * N + j];
            float g1 = (k1 >= 0) ? e[(size_t)k1 * EDIM + lane] : 0.0f;
            float g2 = (k2 >= 0) ? e[(size_t)k2 * EDIM + lane] : 0.0f;
            float g = 0.5f * (g1 + g2);
            const float* shi = g_sh + (size_t)i * 256;
            const float* shj = g_sh + (size_t)j * 256;
#pragma unroll
            for (int t = 0; t < 8; t++) {
                int c = lane + 32 * t;
                a[t] = sBB[c] + shi[c] + shj[c];
            }
#pragma unroll
            for (int q = 0; q < 32; q++) {
                float gq = __shfl_sync(0xffffffffu, g, q);
#pragma unroll
                for (int t = 0; t < 8; t++)
                    a[t] += gq * sW[q * 256 + lane + 32 * t];
            }
            float dx = g_cp[i * 3 + 0] - g_cp[j * 3 + 0];
            float dy = g_cp[i * 3 + 1] - g_cp[j * 3 + 1];
            float dz = g_cp[i * 3 + 2] - g_cp[j * 3 + 2];
            dval = dx * dx + dy * dy + dz * dz;
        } else {
#pragma unroll
            for (int t = 0; t < 8; t++) a[t] = 0.0f;
        }
#pragma unroll
        for (int t = 0; t < 8; t++)
            sEdge[el * EDGE_PITCH + lane + 32 * t] = a[t];
        if (lane == 0) sEdge[el * EDGE_PITCH + 256] = dval;
    }
    __syncthreads();

    // ---- phase 2: z = silu([f,d]@W0 + b0), 8x8 register tile per thread ----
    float acc[8][8];
#pragma unroll
    for (int u = 0; u < 8; u++) {
        int c = lane + 32 * u;
        float b0c = b0[c];
        float w0d = sW0d[c];
#pragma unroll
        for (int v = 0; v < 8; v++)
            acc[u][v] = b0c + sEdge[(wp * 8 + v) * EDGE_PITCH + 256] * w0d;
    }

    for (int kc = 0; kc < 8; kc++) {
        __syncthreads();
        for (int idx = tid; idx < 8192; idx += 256)
            sW[idx] = W0[kc * 32 * 256 + idx];
        __syncthreads();
#pragma unroll
        for (int kk = 0; kk < 32; kk++) {
            int k = kc * 32 + kk;
            float w[8], x[8];
#pragma unroll
            for (int u = 0; u < 8; u++) w[u] = sW[kk * 256 + lane + 32 * u];
#pragma unroll
            for (int v = 0; v < 8; v++) x[v] = sEdge[(wp * 8 + v) * EDGE_PITCH + k];
#pragma unroll
            for (int u = 0; u < 8; u++)
#pragma unroll
                for (int v = 0; v < 8; v++)
                    acc[u][v] += w[u] * x[v];
        }
    }

#pragma unroll
    for (int u = 0; u < 8; u++)
#pragma unroll
        for (int v = 0; v < 8; v++)
            acc[u][v] = silu_f(acc[u][v]);

    // ---- bonds = z @ W1 + b1, warp-shuffle reduce over 32 channel groups ----
#pragma unroll
    for (int v = 0; v < 8; v++) {
        float pb[NBT];
#pragma unroll
        for (int b = 0; b < NBT; b++) pb[b] = 0.0f;
#pragma unroll
        for (int u = 0; u < 8; u++) {
            int c = lane + 32 * u;
            float z = acc[u][v];
#pragma unroll
            for (int b = 0; b < NBT; b++) pb[b] += z * W1[c * NBT + b];
        }
#pragma unroll
        for (int b = 0; b < NBT; b++) {
#pragma unroll
            for (int off = 16; off; off >>= 1)
                pb[b] += __shfl_xor_sync(0xffffffffu, pb[b], off);
        }
        int eg = e0 + wp * 8 + v;
        if (lane == 0 && eg < E) {
#pragma unroll
            for (int b = 0; b < NBT; b++)
                out_bonds[(size_t)eg * NBT + b] = pb[b] + b1[b];
        }
    }
}

// ---------------- launch ----------------
extern "C" void kernel_launch(void* const* d_in, const int* in_sizes, int n_in,
                              void* d_out, int out_size)
{
    const float* s     = (const float*)d_in[0];
    const float* v     = (const float*)d_in[1];
    const float* p     = (const float*)d_in[2];
    const float* e     = (const float*)d_in[3];
    const int*   batch = (const int*)d_in[4];
    const int*   eidx  = (const int*)d_in[5];
    const float* Ws = (const float*)d_in[6];
    const float* bs = (const float*)d_in[7];
    const float* Wc = (const float*)d_in[8];
    const float* Wa = (const float*)d_in[9];
    const float* ba = (const float*)d_in[10];
    const float* Wb = (const float*)d_in[11];
    const float* bb = (const float*)d_in[12];
    const float* W0 = (const float*)d_in[13];
    const float* b0 = (const float*)d_in[14];
    const float* W1 = (const float*)d_in[15];
    const float* b1 = (const float*)d_in[16];

    int N = in_sizes[0] / SDIM;
    int E = in_sizes[5] / 2;

    float* out        = (float*)d_out;
    float* out_coords = out;                    // [N,3]
    float* out_atoms  = out + (size_t)N * 3;    // [N,16]
    float* out_bonds  = out_atoms + (size_t)N * NAF; // [E,5]

    const size_t edge_smem = EDGE_SMEM_FLOATS * sizeof(float);
    cudaFuncSetAttribute(edge_kernel, cudaFuncAttributeMaxDynamicSharedMemorySize,
                         (int)edge_smem);

    int init_blocks = (N * N + 1023) / 1024;
    init_kernel<<<init_blocks, 1024>>>(N);

    sh_kernel<<<(N + 15) / 16, 256>>>(s, Ws, bs, N);

    atoms_kernel<<<(N * 32 + 255) / 256, 256>>>(Wa, ba, out_atoms, N);

    coords_kernel<<<(N * 32 + 255) / 256, 256>>>(v, p, Wc, batch, N);

    finalize_coords_kernel<<<(N * 3 + 255) / 256, 256>>>(batch, out_coords, N);

    scatter_kernel<<<(E + 255) / 256, 256>>>(eidx, N, E);

    edge_kernel<<<(E + 63) / 64, 256, edge_smem>>>(
        e, eidx, Wb, bb, W0, b0, W1, b1, out_bonds, N, E);
}

// round 3
// speedup vs baseline: 3.4770x; 3.4770x over previous
#include <cuda_runtime.h>
#include <cuda_bf16.h>
#include <cstdint>

#define SDIM 256
#define EDIM 32
#define VDIM 64
#define NMOL 64
#define NAF  16
#define NBT  5
#define MAXN 2048
#define ETILE 128

// ---------------- device scratch (no allocs allowed) ----------------
__device__ float g_sh[MAXN * SDIM];        // s_h = silu(s@Ws+bs)
__device__ float g_T [MAXN * SDIM];        // T = s_h @ W0'
__device__ float g_raw[MAXN * 3];
__device__ float g_cp[MAXN * 3];
__device__ float g_sums[NMOL * 3];
__device__ float g_cnt[NMOL];
__device__ int   g_map[MAXN * MAXN];       // last-writer edge index per (j,i)
__device__ float g_wbw0[EDIM * SDIM];      // Wb @ W0'
__device__ float g_cvec[SDIM];             // bb @ W0' + b0

__device__ __forceinline__ float silu_f(float x) {
    return __fdividef(x, 1.0f + __expf(-x));
}

// ---------------- init: map=-1, sums/cnt=0 ----------------
__global__ void init_kernel(int N) {
    int idx = blockIdx.x * blockDim.x + threadIdx.x;
    int total = N * N;
    for (int i = idx; i < total; i += gridDim.x * blockDim.x) g_map[i] = -1;
    if (idx < NMOL * 3) g_sums[idx] = 0.0f;
    if (idx < NMOL)     g_cnt[idx]  = 0.0f;
}

// ---------------- 256x256 row GEMM over device-global scratch ----------------
// MODE 0: g_sh = silu(X_ext @ W + bias)
// MODE 1: g_T  = g_sh @ W          (no bias, no act)
// NOTE: scratch buffers are selected INSIDE device code — passing __device__
// symbols as host-side kernel args resolves to the host shadow address (R2 bug).
template<int MODE>
__global__ __launch_bounds__(256) void rowgemm_kernel(
    const float* __restrict__ X_ext, const float* __restrict__ W,
    const float* __restrict__ bias, int N)
{
    const float* X = (MODE == 0) ? X_ext : (const float*)g_sh;
    float*       out = (MODE == 0) ? g_sh : g_T;

    __shared__ float sX[16 * 256];
    __shared__ float sW[32 * 256];
    int tid = threadIdx.x, lane = tid & 31, wp = tid >> 5;
    int row0 = blockIdx.x * 16;

    for (int idx = tid; idx < 16 * 256; idx += 256) {
        int g = row0 * 256 + idx;
        sX[idx] = (g < N * 256) ? X[g] : 0.0f;
    }

    float acc[8][2];
#pragma unroll
    for (int u = 0; u < 8; u++) {
        float b = (MODE == 0) ? bias[lane + 32 * u] : 0.0f;
        acc[u][0] = b; acc[u][1] = b;
    }

    for (int kc = 0; kc < 8; kc++) {
        __syncthreads();
        for (int idx = tid; idx < 8192; idx += 256)
            sW[idx] = W[kc * 32 * 256 + idx];
        __syncthreads();
#pragma unroll
        for (int kk = 0; kk < 32; kk++) {
            float w[8];
#pragma unroll
            for (int u = 0; u < 8; u++) w[u] = sW[kk * 256 + lane + 32 * u];
            float x0 = sX[(wp * 2 + 0) * 256 + kc * 32 + kk];
            float x1 = sX[(wp * 2 + 1) * 256 + kc * 32 + kk];
#pragma unroll
            for (int u = 0; u < 8; u++) {
                acc[u][0] += w[u] * x0;
                acc[u][1] += w[u] * x1;
            }
        }
    }
#pragma unroll
    for (int v = 0; v < 2; v++) {
        int r = row0 + wp * 2 + v;
        if (r < N) {
#pragma unroll
            for (int u = 0; u < 8; u++) {
                float y = acc[u][v];
                out[r * 256 + lane + 32 * u] = (MODE == 0) ? silu_f(y) : y;
            }
        }
    }
}

// ---------------- WbW0 = Wb @ W0' (blocks 0..31) ; cvec = bb@W0'+b0 (block 32) ----------------
__global__ void foldw_kernel(const float* __restrict__ Wb, const float* __restrict__ W0,
                             const float* __restrict__ bb, const float* __restrict__ b0)
{
    int c = threadIdx.x;
    int r = blockIdx.x;
    if (r < EDIM) {
        float acc = 0.0f;
        for (int m = 0; m < SDIM; m++)
            acc += Wb[r * SDIM + m] * W0[m * SDIM + c];
        g_wbw0[r * SDIM + c] = acc;
    } else {
        float acc = b0[c];
        for (int m = 0; m < SDIM; m++)
            acc += bb[m] * W0[m * SDIM + c];
        g_cvec[c] = acc;
    }
}

// ---------------- atoms_pred = s_h @ Wa + ba (one warp per node) ----------------
__global__ void atoms_kernel(const float* __restrict__ Wa, const float* __restrict__ ba,
                             float* __restrict__ out_atoms, int N)
{
    int wg = (blockIdx.x * blockDim.x + threadIdx.x) >> 5;
    int lane = threadIdx.x & 31;
    if (wg >= N) return;
    const float* row = g_sh + (size_t)wg * 256;
    float acc[NAF];
#pragma unroll
    for (int a = 0; a < NAF; a++) acc[a] = 0.0f;
#pragma unroll
    for (int m = 0; m < 8; m++) {
        int c = lane + 32 * m;
        float x = row[c];
#pragma unroll
        for (int a = 0; a < NAF; a++) acc[a] += x * Wa[c * NAF + a];
    }
#pragma unroll
    for (int a = 0; a < NAF; a++) {
#pragma unroll
        for (int off = 16; off; off >>= 1)
            acc[a] += __shfl_xor_sync(0xffffffffu, acc[a], off);
    }
#pragma unroll
    for (int a = 0; a < NAF; a++)
        if (lane == a) out_atoms[(size_t)wg * NAF + a] = acc[a] + ba[a];
}

// ---------------- coords / per-mol sums ----------------
__global__ void coords_kernel(const float* __restrict__ v, const float* __restrict__ p,
                              const float* __restrict__ Wc, const int* __restrict__ batch, int N)
{
    int n = (blockIdx.x * blockDim.x + threadIdx.x) >> 5;
    int lane = threadIdx.x & 31;
    if (n >= N) return;
    const float* vb = v + (size_t)n * 3 * VDIM;
    float w0 = Wc[lane], w1 = Wc[32 + lane];
    float a0 = vb[lane] * w0 + vb[32 + lane] * w1;
    float a1 = vb[64 + lane] * w0 + vb[96 + lane] * w1;
    float a2 = vb[128 + lane] * w0 + vb[160 + lane] * w1;
#pragma unroll
    for (int off = 16; off; off >>= 1) {
        a0 += __shfl_xor_sync(0xffffffffu, a0, off);
        a1 += __shfl_xor_sync(0xffffffffu, a1, off);
        a2 += __shfl_xor_sync(0xffffffffu, a2, off);
    }
    if (lane == 0) {
        int b = batch[n];
        float r0 = p[n * 3 + 0] + a0;
        float r1 = p[n * 3 + 1] + a1;
        float r2 = p[n * 3 + 2] + a2;
        g_raw[n * 3 + 0] = r0; g_raw[n * 3 + 1] = r1; g_raw[n * 3 + 2] = r2;
        atomicAdd(&g_sums[b * 3 + 0], r0);
        atomicAdd(&g_sums[b * 3 + 1], r1);
        atomicAdd(&g_sums[b * 3 + 2], r2);
        atomicAdd(&g_cnt[b], 1.0f);
    }
}

__global__ void finalize_coords_kernel(const int* __restrict__ batch,
                                       float* __restrict__ out_coords, int N)
{
    int idx = blockIdx.x * blockDim.x + threadIdx.x;
    if (idx >= N * 3) return;
    int n = idx / 3, d = idx % 3;
    int b = batch[n];
    float m = g_sums[b * 3 + d] / fmaxf(g_cnt[b], 1.0f);
    float cp = g_raw[idx] - m;
    g_cp[idx] = cp;
    out_coords[idx] = cp;
}

// ---------------- last-writer scatter ----------------
__global__ void scatter_kernel(const int* __restrict__ eidx, int N, int E)
{
    int k = blockIdx.x * blockDim.x + threadIdx.x;
    if (k >= E) return;
    int j = eidx[k];
    int i = eidx[E + k];
    atomicMax(&g_map[j * N + i], k);
}

// ---------------- fused edge network (folded form) ----------------
// y = T[i] + T[j] + e_sym@WbW0 + cvec + d*w0d ; z=silu(y) ; bonds = z@W1 + b1
#define EDGE_SMEM_BYTES ((8192 + 1280 + 256 + 256 + 4096 + 128) * 4 + 4 * 128 * 4)

__device__ __forceinline__ unsigned long long dup_f32x2(float x) {
    unsigned long long r;
    asm("mov.b64 %0, {%1, %1};" : "=l"(r) : "r"(__float_as_uint(x)));
    return r;
}
__device__ __forceinline__ void ffma2(unsigned long long& acc,
                                      unsigned long long a, unsigned long long b) {
    asm("fma.rn.f32x2 %0, %1, %2, %0;" : "+l"(acc) : "l"(a), "l"(b));
}
__device__ __forceinline__ float2 unpack2(unsigned long long x) {
    float2 r;
    asm("mov.b64 {%0, %1}, %2;" : "=f"(r.x), "=f"(r.y) : "l"(x));
    return r;
}

__global__ __launch_bounds__(256, 2) void edge_kernel(
    const float* __restrict__ e, const int* __restrict__ eidx,
    const float* __restrict__ W0, const float* __restrict__ W1,
    const float* __restrict__ b1,
    float* __restrict__ out_bonds, int N, int E)
{
    extern __shared__ float sm[];
    float* sW   = sm;                 // [32][256] WbW0
    float* sW1T = sW + 8192;          // [5][256]
    float* scv  = sW1T + 1280;        // [256]
    float* sw0  = scv + 256;          // [256] W0 row 256 (d weights)
    float* sg   = sw0 + 256;          // [128][32]
    float* sd   = sg + 4096;          // [128]
    int*   sI   = (int*)(sd + 128);
    int*   sJ   = sI + 128;
    int*   sK1  = sJ + 128;
    int*   sK2  = sK1 + 128;

    int tid = threadIdx.x, lane = tid & 31, wp = tid >> 5;
    int e0 = blockIdx.x * ETILE;

    for (int idx = tid; idx < 8192; idx += 256) sW[idx] = g_wbw0[idx];
    for (int idx = tid; idx < 1280; idx += 256) {
        int b = idx >> 8, c = idx & 255;
        sW1T[idx] = W1[c * NBT + b];
    }
    if (tid < 256) { scv[tid] = g_cvec[tid]; sw0[tid] = W0[256 * 256 + tid]; }

    // ---- phase A: per-edge meta ----
    if (tid < ETILE) {
        int eg = e0 + tid;
        int i = 0, j = 0, k1 = -1, k2 = -1;
        float dval = 0.0f;
        if (eg < E) {
            j = eidx[eg];
            i = eidx[E + eg];
            k1 = g_map[j * N + i];
            k2 = g_map[i * N + j];
            float dx = g_cp[i * 3 + 0] - g_cp[j * 3 + 0];
            float dy = g_cp[i * 3 + 1] - g_cp[j * 3 + 1];
            float dz = g_cp[i * 3 + 2] - g_cp[j * 3 + 2];
            dval = dx * dx + dy * dy + dz * dz;
        }
        sI[tid] = i; sJ[tid] = j; sK1[tid] = k1; sK2[tid] = k2; sd[tid] = dval;
    }
    __syncthreads();

    // ---- load symmetrized e rows ----
    for (int idx = tid; idx < ETILE * 32; idx += 256) {
        int el = idx >> 5, q = idx & 31;
        int k1 = sK1[el], k2 = sK2[el];
        float g1 = (k1 >= 0) ? e[(size_t)k1 * EDIM + q] : 0.0f;
        float g2 = (k2 >= 0) ? e[(size_t)k2 * EDIM + q] : 0.0f;
        sg[idx] = 0.5f * (g1 + g2);
    }
    __syncthreads();

    // ---- phase B: each warp handles 16 edges in 2 sub-passes of 8 ----
    for (int sub = 0; sub < 2; sub++) {
        int base = wp * 16 + sub * 8;

        float gv[8];
#pragma unroll
        for (int v = 0; v < 8; v++) gv[v] = sg[(base + v) * 32 + lane];

        unsigned long long acc[4][8];
#pragma unroll
        for (int t = 0; t < 4; t++)
#pragma unroll
            for (int v = 0; v < 8; v++) acc[t][v] = 0ull;

#pragma unroll 8
        for (int q = 0; q < 32; q++) {
            unsigned long long wq[4];
#pragma unroll
            for (int t = 0; t < 4; t++)
                wq[t] = *(const unsigned long long*)&sW[q * 256 + 2 * lane + 64 * t];
#pragma unroll
            for (int v = 0; v < 8; v++) {
                float gq = __shfl_sync(0xffffffffu, gv[v], q);
                unsigned long long g2 = dup_f32x2(gq);
#pragma unroll
                for (int t = 0; t < 4; t++) ffma2(acc[t][v], wq[t], g2);
            }
        }

        // ---- epilogue per edge ----
#pragma unroll 2
        for (int v = 0; v < 8; v++) {
            int el = base + v;
            int eg = e0 + el;
            int i = sI[el], jn = sJ[el];
            float dval = sd[el];
            const float* Ti = g_T + (size_t)i * 256;
            const float* Tj = g_T + (size_t)jn * 256;

            unsigned long long zp[4];
#pragma unroll
            for (int t = 0; t < 4; t++) {
                int c0 = 2 * lane + 64 * t;
                float2 a  = unpack2(acc[t][v]);
                float2 ti = *(const float2*)&Ti[c0];
                float2 tj = *(const float2*)&Tj[c0];
                float2 cv = *(const float2*)&scv[c0];
                float2 wd = *(const float2*)&sw0[c0];
                float y0 = a.x + cv.x + ti.x + tj.x + dval * wd.x;
                float y1 = a.y + cv.y + ti.y + tj.y + dval * wd.y;
                float z0 = silu_f(y0);
                float z1 = silu_f(y1);
                unsigned long long zpk;
                asm("mov.b64 %0, {%1, %2};" : "=l"(zpk)
                    : "r"(__float_as_uint(z0)), "r"(__float_as_uint(z1)));
                zp[t] = zpk;
            }

            unsigned long long pbp[NBT];
#pragma unroll
            for (int b = 0; b < NBT; b++) pbp[b] = 0ull;
#pragma unroll
            for (int t = 0; t < 4; t++) {
                int c0 = 2 * lane + 64 * t;
#pragma unroll
                for (int b = 0; b < NBT; b++) {
                    unsigned long long w1p =
                        *(const unsigned long long*)&sW1T[b * 256 + c0];
                    ffma2(pbp[b], zp[t], w1p);
                }
            }
            float pb[NBT];
#pragma unroll
            for (int b = 0; b < NBT; b++) {
                float2 u = unpack2(pbp[b]);
                pb[b] = u.x + u.y;
            }
#pragma unroll
            for (int b = 0; b < NBT; b++) {
#pragma unroll
                for (int off = 16; off; off >>= 1)
                    pb[b] += __shfl_xor_sync(0xffffffffu, pb[b], off);
            }
            if (lane == 0 && eg < E) {
#pragma unroll
                for (int b = 0; b < NBT; b++)
                    out_bonds[(size_t)eg * NBT + b] = pb[b] + b1[b];
            }
        }
    }
}

// ---------------- launch ----------------
extern "C" void kernel_launch(void* const* d_in, const int* in_sizes, int n_in,
                              void* d_out, int out_size)
{
    const float* s     = (const float*)d_in[0];
    const float* v     = (const float*)d_in[1];
    const float* p     = (const float*)d_in[2];
    const float* e     = (const float*)d_in[3];
    const int*   batch = (const int*)d_in[4];
    const int*   eidx  = (const int*)d_in[5];
    const float* Ws = (const float*)d_in[6];
    const float* bs = (const float*)d_in[7];
    const float* Wc = (const float*)d_in[8];
    const float* Wa = (const float*)d_in[9];
    const float* ba = (const float*)d_in[10];
    const float* Wb = (const float*)d_in[11];
    const float* bb = (const float*)d_in[12];
    const float* W0 = (const float*)d_in[13];
    const float* b0 = (const float*)d_in[14];
    const float* W1 = (const float*)d_in[15];
    const float* b1 = (const float*)d_in[16];

    int N = in_sizes[0] / SDIM;
    int E = in_sizes[5] / 2;

    float* out        = (float*)d_out;
    float* out_coords = out;
    float* out_atoms  = out + (size_t)N * 3;
    float* out_bonds  = out_atoms + (size_t)N * NAF;

    cudaFuncSetAttribute(edge_kernel, cudaFuncAttributeMaxDynamicSharedMemorySize,
                         EDGE_SMEM_BYTES);

    int init_blocks = (N * N + 1023) / 1024;
    init_kernel<<<init_blocks, 1024>>>(N);

    // s_h = silu(s@Ws+bs)  -> g_sh (selected in device code)
    rowgemm_kernel<0><<<(N + 15) / 16, 256>>>(s, Ws, bs, N);

    // T = s_h @ W0' -> g_T (selected in device code)
    rowgemm_kernel<1><<<(N + 15) / 16, 256>>>(nullptr, W0, nullptr, N);

    // fold Wb@W0' and bb@W0'+b0
    foldw_kernel<<<EDIM + 1, 256>>>(Wb, W0, bb, b0);

    atoms_kernel<<<(N * 32 + 255) / 256, 256>>>(Wa, ba, out_atoms, N);

    coords_kernel<<<(N * 32 + 255) / 256, 256>>>(v, p, Wc, batch, N);

    finalize_coords_kernel<<<(N * 3 + 255) / 256, 256>>>(batch, out_coords, N);

    scatter_kernel<<<(E + 255) / 256, 256>>>(eidx, N, E);

    edge_kernel<<<(E + ETILE - 1) / ETILE, 256, EDGE_SMEM_BYTES>>>(
        e, eidx, W0, W1, b1, out_bonds, N, E);
}